// round 4
// baseline (speedup 1.0000x reference)
#include <cuda_runtime.h>
#include <cuda_bf16.h>

#define NBLOCKS 1184          // 148 SMs * 8 CTAs, single wave (2048 thr/SM)
#define NTHREADS 256

__device__ float g_partials[NBLOCKS];
__device__ unsigned int g_ticket = 0;   // reset by last block each call -> graph-replay safe

__global__ __launch_bounds__(NTHREADS)
void sumsq_fused_kernel(const float* __restrict__ w, long nw,
                        const float* __restrict__ b, long nb,
                        float* __restrict__ out) {
    const long nw4 = nw >> 2;
    const long nb4 = nb >> 2;
    const float4* __restrict__ w4 = reinterpret_cast<const float4*>(w);
    const float4* __restrict__ b4 = reinterpret_cast<const float4*>(b);

    const long idx    = (long)blockIdx.x * NTHREADS + threadIdx.x;
    const long stride = (long)gridDim.x * NTHREADS;

    float acc = 0.0f;

    // Round-1 proven loop body: simple grid-stride float4; ptxas front-batches loads.
    for (long i = idx; i < nw4; i += stride) {
        float4 v = w4[i];
        acc += v.x * v.x + v.y * v.y + v.z * v.z + v.w * v.w;
    }
    for (long i = idx; i < nb4; i += stride) {
        float4 v = b4[i];
        acc += v.x * v.x + v.y * v.y + v.z * v.z + v.w * v.w;
    }
    // scalar tails (no-op for these shapes)
    for (long i = (nw4 << 2) + idx; i < nw; i += stride) { float v = w[i]; acc += v * v; }
    for (long i = (nb4 << 2) + idx; i < nb; i += stride) { float v = b[i]; acc += v * v; }

    // warp reduce
    #pragma unroll
    for (int o = 16; o > 0; o >>= 1)
        acc += __shfl_xor_sync(0xffffffffu, acc, o);

    __shared__ float s[NTHREADS / 32];
    __shared__ bool  is_last;
    if ((threadIdx.x & 31) == 0) s[threadIdx.x >> 5] = acc;
    __syncthreads();

    if (threadIdx.x < 32) {
        acc = (threadIdx.x < NTHREADS / 32) ? s[threadIdx.x] : 0.0f;
        #pragma unroll
        for (int o = 16; o > 0; o >>= 1)
            acc += __shfl_xor_sync(0xffffffffu, acc, o);
        if (threadIdx.x == 0) {
            g_partials[blockIdx.x] = acc;
            __threadfence();
            unsigned int t = atomicAdd(&g_ticket, 1u);
            is_last = (t == (unsigned int)gridDim.x - 1u);
        }
    }
    __syncthreads();

    // Last-arriving block: deterministic fixed-order reduce of all partials.
    if (is_last) {
        float f = 0.0f;
        for (int k = threadIdx.x; k < NBLOCKS; k += NTHREADS)
            f += g_partials[k];

        #pragma unroll
        for (int o = 16; o > 0; o >>= 1)
            f += __shfl_xor_sync(0xffffffffu, f, o);

        if ((threadIdx.x & 31) == 0) s[threadIdx.x >> 5] = f;
        __syncthreads();

        if (threadIdx.x < 32) {
            f = (threadIdx.x < NTHREADS / 32) ? s[threadIdx.x] : 0.0f;
            #pragma unroll
            for (int o = 16; o > 0; o >>= 1)
                f += __shfl_xor_sync(0xffffffffu, f, o);
            if (threadIdx.x == 0) {
                out[0] = 0.12f * f;   // (2+4+6)*LAMB; segment sums re-total to full sum
                g_ticket = 0;         // reset for next graph replay
            }
        }
    }
}

extern "C" void kernel_launch(void* const* d_in, const int* in_sizes, int n_in,
                              void* d_out, int out_size) {
    const float* w = (const float*)d_in[0];   // fc_weights
    const float* b = (const float*)d_in[1];   // fc_bias
    // d_in[2] = coarse_map: algebraically irrelevant
    float* out = (float*)d_out;

    long nw = (long)in_sizes[0];
    long nb = (long)in_sizes[1];

    sumsq_fused_kernel<<<NBLOCKS, NTHREADS>>>(w, nw, b, nb, out);
}

// round 5
// speedup vs baseline: 1.0484x; 1.0484x over previous
#include <cuda_runtime.h>
#include <cuda_bf16.h>

#define NBLOCKS 1184          // 148 SMs * 8 CTAs, single wave
#define NTHREADS 256
#define CHUNK (4 * NTHREADS)  // 1024 float4 = 16 KB per block-chunk

__device__ float g_partials[NBLOCKS];
__device__ unsigned int g_ticket = 0;   // reset by last block -> graph-replay safe

__global__ __launch_bounds__(NTHREADS)
void sumsq_fused_kernel(const float* __restrict__ w, long nw,
                        const float* __restrict__ b, long nb,
                        float* __restrict__ out) {
    const long nw4 = nw >> 2;
    const long nb4 = nb >> 2;
    const float4* __restrict__ w4 = reinterpret_cast<const float4*>(w);
    const float4* __restrict__ b4 = reinterpret_cast<const float4*>(b);

    float a0 = 0.f, a1 = 0.f, a2 = 0.f, a3 = 0.f;

    // Block-contiguous chunks: 4 independent LDG.128 per thread per iteration,
    // all within one contiguous 16KB chunk (DRAM page locality + MLP=4).
    for (long base = (long)blockIdx.x * CHUNK; base < nw4;
         base += (long)gridDim.x * CHUNK) {
        long i0 = base + threadIdx.x;
        long i1 = i0 + NTHREADS;
        long i2 = i0 + 2 * NTHREADS;
        long i3 = i0 + 3 * NTHREADS;
        if (i3 < nw4) {                      // fast path: whole chunk in-bounds
            float4 v0 = w4[i0];
            float4 v1 = w4[i1];
            float4 v2 = w4[i2];
            float4 v3 = w4[i3];
            a0 += v0.x * v0.x + v0.y * v0.y + v0.z * v0.z + v0.w * v0.w;
            a1 += v1.x * v1.x + v1.y * v1.y + v1.z * v1.z + v1.w * v1.w;
            a2 += v2.x * v2.x + v2.y * v2.y + v2.z * v2.z + v2.w * v2.w;
            a3 += v3.x * v3.x + v3.y * v3.y + v3.z * v3.z + v3.w * v3.w;
        } else {
            if (i0 < nw4) { float4 v = w4[i0]; a0 += v.x*v.x + v.y*v.y + v.z*v.z + v.w*v.w; }
            if (i1 < nw4) { float4 v = w4[i1]; a1 += v.x*v.x + v.y*v.y + v.z*v.z + v.w*v.w; }
            if (i2 < nw4) { float4 v = w4[i2]; a2 += v.x*v.x + v.y*v.y + v.z*v.z + v.w*v.w; }
            if (i3 < nw4) { float4 v = w4[i3]; a3 += v.x*v.x + v.y*v.y + v.z*v.z + v.w*v.w; }
        }
    }

    // bias (tiny): simple grid-stride
    {
        const long idx    = (long)blockIdx.x * NTHREADS + threadIdx.x;
        const long stride = (long)gridDim.x * NTHREADS;
        for (long i = idx; i < nb4; i += stride) {
            float4 v = b4[i];
            a0 += v.x * v.x + v.y * v.y + v.z * v.z + v.w * v.w;
        }
        // scalar tails (no-op for these shapes)
        for (long i = (nw4 << 2) + idx; i < nw; i += stride) { float v = w[i]; a1 += v * v; }
        for (long i = (nb4 << 2) + idx; i < nb; i += stride) { float v = b[i]; a2 += v * v; }
    }

    float acc = (a0 + a1) + (a2 + a3);

    // warp reduce
    #pragma unroll
    for (int o = 16; o > 0; o >>= 1)
        acc += __shfl_xor_sync(0xffffffffu, acc, o);

    __shared__ float s[NTHREADS / 32];
    __shared__ bool  is_last;
    if ((threadIdx.x & 31) == 0) s[threadIdx.x >> 5] = acc;
    __syncthreads();

    if (threadIdx.x < 32) {
        acc = (threadIdx.x < NTHREADS / 32) ? s[threadIdx.x] : 0.0f;
        #pragma unroll
        for (int o = 16; o > 0; o >>= 1)
            acc += __shfl_xor_sync(0xffffffffu, acc, o);
        if (threadIdx.x == 0) {
            g_partials[blockIdx.x] = acc;
            __threadfence();
            unsigned int t = atomicAdd(&g_ticket, 1u);
            is_last = (t == (unsigned int)gridDim.x - 1u);
        }
    }
    __syncthreads();

    // Last-arriving block: deterministic fixed-order reduce of all partials.
    if (is_last) {
        float f = 0.0f;
        for (int k = threadIdx.x; k < NBLOCKS; k += NTHREADS)
            f += g_partials[k];

        #pragma unroll
        for (int o = 16; o > 0; o >>= 1)
            f += __shfl_xor_sync(0xffffffffu, f, o);

        if ((threadIdx.x & 31) == 0) s[threadIdx.x >> 5] = f;
        __syncthreads();

        if (threadIdx.x < 32) {
            f = (threadIdx.x < NTHREADS / 32) ? s[threadIdx.x] : 0.0f;
            #pragma unroll
            for (int o = 16; o > 0; o >>= 1)
                f += __shfl_xor_sync(0xffffffffu, f, o);
            if (threadIdx.x == 0) {
                out[0] = 0.12f * f;   // (2+4+6)*LAMB; segment sums re-total to full sum
                g_ticket = 0;         // reset for next graph replay
            }
        }
    }
}

extern "C" void kernel_launch(void* const* d_in, const int* in_sizes, int n_in,
                              void* d_out, int out_size) {
    const float* w = (const float*)d_in[0];   // fc_weights
    const float* b = (const float*)d_in[1];   // fc_bias
    // d_in[2] = coarse_map: algebraically irrelevant
    float* out = (float*)d_out;

    long nw = (long)in_sizes[0];
    long nb = (long)in_sizes[1];

    sumsq_fused_kernel<<<NBLOCKS, NTHREADS>>>(w, nw, b, nb, out);
}